// round 7
// baseline (speedup 1.0000x reference)
#include <cuda_runtime.h>
#include <cuda_bf16.h>

// SAN Subtraction: out[n,c,kk,p] = x[n,c,h,w] - reflectpad(x)[n,c,h+kh,w+kw]
// N=4, C=64, H=W=112, K=7, PAD=3, reflect. out (N,C,49,12544) fp32 = 630 MB writes.
// v7 = v6 (best: linear warp mapping, 3x LDG.128 neighbor span + register-move
// reflect fixups, __stcs streaming stores) with occupancy raised 59% -> ~87%
// via __launch_bounds__(224, 8): single-variable probe of store-MLP vs the
// ~74% DRAM ceiling observed across all five prior kernel shapes.

#define H 112
#define W 112
#define KS 7
#define PADV 3
#define HW (H * W)            // 12544
#define CC 64
#define NN 4
#define W4N 28                // float4s per row
#define TPB 224               // 7 warps; 224 float4s/block; 14 blocks/plane

__device__ __forceinline__ int reflect_h(int j) {
    j = j < 0 ? -j : j;
    j = j >= H ? (2 * (H - 1) - j) : j;
    return j;
}

__global__ void __launch_bounds__(TPB, 8) san_sub_kernel(
    const float* __restrict__ x, float* __restrict__ out)
{
    const int i  = blockIdx.x * TPB + threadIdx.x;   // float4 index in plane
    const int h  = i / W4N;
    const int w4 = (i - h * W4N) << 2;               // 0,4,...,108
    const int plane = blockIdx.z * CC + blockIdx.y;  // n*64 + c

    const bool pL = (w4 != 0);
    const bool pR = (w4 != W - 4);

    const float* xp = x + (size_t)plane * HW;
    float* op = out + (size_t)plane * (KS * KS) * HW + ((size_t)i << 2);

    const float4 ctr = *reinterpret_cast<const float4*>(xp + ((size_t)i << 2));

    #pragma unroll
    for (int kh = 0; kh < KS; ++kh) {
        const int rh = reflect_h(h + kh - PADV);
        const float* row = xp + rh * W;

        // v[j] = x[row, w4-4+j], j=0..11 (interior); edges fixed by reg moves
        float v[12];
        if (pL) *reinterpret_cast<float4*>(&v[0]) =
                    *reinterpret_cast<const float4*>(row + w4 - 4);
        *reinterpret_cast<float4*>(&v[4]) =
                    *reinterpret_cast<const float4*>(row + w4);
        if (pR) *reinterpret_cast<float4*>(&v[8]) =
                    *reinterpret_cast<const float4*>(row + w4 + 4);
        if (!pL) {            // w4==0: x[-3,-2,-1] -> x[3,2,1]
            v[1] = v[7]; v[2] = v[6]; v[3] = v[5];
        }
        if (!pR) {            // w4==108: x[112,113,114] -> x[110,109,108]
            v[8] = v[6]; v[9] = v[5]; v[10] = v[4];
        }

        #pragma unroll
        for (int kw = 0; kw < KS; ++kw) {
            float4 o;
            o.x = ctr.x - v[kw + 1];
            o.y = ctr.y - v[kw + 2];
            o.z = ctr.z - v[kw + 3];
            o.w = ctr.w - v[kw + 4];
            __stcs(reinterpret_cast<float4*>(op + (size_t)(kh * KS + kw) * HW), o);
        }
    }
}

extern "C" void kernel_launch(void* const* d_in, const int* in_sizes, int n_in,
                              void* d_out, int out_size) {
    const float* x = (const float*)d_in[0];
    float* out = (float*)d_out;
    dim3 block(TPB, 1, 1);
    dim3 grid(HW / 4 / TPB, CC, NN);   // (14, 64, 4) = 3584 blocks
    san_sub_kernel<<<grid, block>>>(x, out);
}

// round 8
// speedup vs baseline: 1.0850x; 1.0850x over previous
#include <cuda_runtime.h>
#include <cuda_bf16.h>

// SAN Subtraction: out[n,c,kk,p] = x[n,c,h,w] - reflectpad(x)[n,c,h+kh,w+kw]
// N=4, C=64, H=W=112, K=7, PAD=3, reflect. out (N,C,49,12544) fp32 = 630 MB writes.
// v8: wave-quantization fix. R7 evidence: grid 3584 @ conc 1184 = 3.03 waves
// quantized to 4 -> DRAM avg 75.5% == 3.03/4 of a ~full-rate steady state.
// Split work per-kh: one block = (plane, kh, chunk) -> 25088 small blocks,
// occ 9 (conc 1332) -> 18.8 -> 19 waves = 99% wave efficiency.
// Per thread: 1 ctr LDG.128 + 3 neighbor LDG.128 (reg-move reflect fixups),
// 7 STG.128 streaming stores.

#define H 112
#define W 112
#define KS 7
#define PADV 3
#define HW (H * W)            // 12544
#define CC 64
#define NN 4
#define W4N 28                // float4s per row
#define TPB 224               // 7 warps; 224 float4s/block; 14 chunks/plane

__device__ __forceinline__ int reflect_h(int j) {
    j = j < 0 ? -j : j;
    j = j >= H ? (2 * (H - 1) - j) : j;
    return j;
}

__global__ void __launch_bounds__(TPB, 9) san_sub_kernel(
    const float* __restrict__ x, float* __restrict__ out)
{
    const int i  = blockIdx.x * TPB + threadIdx.x;   // float4 index in plane
    const int kh = blockIdx.y;                       // 0..6
    const int plane = blockIdx.z;                    // n*64 + c, 0..255
    const int h  = i / W4N;
    const int w4 = (i - h * W4N) << 2;               // 0,4,...,108

    const bool pL = (w4 != 0);
    const bool pR = (w4 != W - 4);

    const float* xp = x + (size_t)plane * HW;
    float* op = out + ((size_t)plane * (KS * KS) + kh * KS) * HW + ((size_t)i << 2);

    const float4 ctr = *reinterpret_cast<const float4*>(xp + ((size_t)i << 2));

    const int rh = reflect_h(h + kh - PADV);
    const float* row = xp + rh * W;

    // v[j] = x[row, w4-4+j], j=0..11 (interior); edges fixed by reg moves
    float v[12];
    if (pL) *reinterpret_cast<float4*>(&v[0]) =
                *reinterpret_cast<const float4*>(row + w4 - 4);
    *reinterpret_cast<float4*>(&v[4]) =
                *reinterpret_cast<const float4*>(row + w4);
    if (pR) *reinterpret_cast<float4*>(&v[8]) =
                *reinterpret_cast<const float4*>(row + w4 + 4);
    if (!pL) {            // w4==0: x[-3,-2,-1] -> x[3,2,1]
        v[1] = v[7]; v[2] = v[6]; v[3] = v[5];
    }
    if (!pR) {            // w4==108: x[112,113,114] -> x[110,109,108]
        v[8] = v[6]; v[9] = v[5]; v[10] = v[4];
    }

    #pragma unroll
    for (int kw = 0; kw < KS; ++kw) {
        float4 o;
        o.x = ctr.x - v[kw + 1];
        o.y = ctr.y - v[kw + 2];
        o.z = ctr.z - v[kw + 3];
        o.w = ctr.w - v[kw + 4];
        __stcs(reinterpret_cast<float4*>(op + (size_t)kw * HW), o);
    }
}

extern "C" void kernel_launch(void* const* d_in, const int* in_sizes, int n_in,
                              void* d_out, int out_size) {
    const float* x = (const float*)d_in[0];
    float* out = (float*)d_out;
    dim3 block(TPB, 1, 1);
    dim3 grid(HW / 4 / TPB, KS, CC * NN);   // (14, 7, 256) = 25088 blocks
    san_sub_kernel<<<grid, block>>>(x, out);
}